// round 12
// baseline (speedup 1.0000x reference)
#include <cuda_runtime.h>
#include <cuda_fp16.h>
#include <math.h>
#include <cstdint>

#define N_NODES 50000
#define N_EDGES 800000
#define TILE_E  64
#define N_TILES (N_EDGES / TILE_E)   // 12500
#define EDGE_CTAS 592                // 4 per SM
#define NGRP    (N_NODES / 16)       // 3125 exact

// Device scratch (no allocs allowed).
__device__ float    g_msum[N_NODES * 64];
__device__ uint32_t g_Ph[N_NODES * 32];   // half2: feat@W1a + b1
__device__ uint32_t g_Qh[N_NODES * 32];   // half2: feat@W1b
__device__ float    g_sqd[N_EDGES];

// fragment permutation within each 8-slot group
__host__ __device__ __forceinline__ int kpos(int s) {
    return (s & ~7) + 2 * (s & 3) + ((s >> 2) & 1);
}
__device__ __forceinline__ void mma16h(float d[4], uint32_t a0, uint32_t a1,
                                       uint32_t a2, uint32_t a3,
                                       uint32_t b0, uint32_t b1) {
    asm("mma.sync.aligned.m16n8k16.row.col.f32.f16.f16.f32 "
        "{%0,%1,%2,%3}, {%4,%5,%6,%7}, {%8,%9}, {%0,%1,%2,%3};"
        : "+f"(d[0]), "+f"(d[1]), "+f"(d[2]), "+f"(d[3])
        : "r"(a0), "r"(a1), "r"(a2), "r"(a3), "r"(b0), "r"(b1));
}
__device__ __forceinline__ void red4(float* p, float a, float b, float c, float d) {
    asm volatile("red.global.add.v4.f32 [%0], {%1,%2,%3,%4};"
                 :: "l"(p), "f"(a), "f"(b), "f"(c), "f"(d) : "memory");
}
__device__ __forceinline__ uint32_t h2pack(float a, float b) {
    __half2 hv = __floats2half2_rn(a, b);
    return *reinterpret_cast<uint32_t*>(&hv);
}
__device__ __forceinline__ float2 h2unpack(uint32_t u) {
    return __half22float2(*reinterpret_cast<__half2*>(&u));
}

// ---------------------------------------------------------------------------
// zs_kernel: zero g_msum + per-edge squared distance (streaming, big grid)
// ---------------------------------------------------------------------------
__global__ __launch_bounds__(256) void zs_kernel(
    const float* __restrict__ x,
    const int* __restrict__ src, const int* __restrict__ dst)
{
    const int gid = blockIdx.x * 256 + threadIdx.x;
    const int gs  = gridDim.x * 256;
    for (int i = gid; i < N_NODES * 16; i += gs)
        reinterpret_cast<float4*>(g_msum)[i] = make_float4(0.f, 0.f, 0.f, 0.f);
    for (int e = gid; e < N_EDGES; e += gs) {
        const int s = src[e], d = dst[e];
        float dx = x[3 * s + 0] - x[3 * d + 0];
        float dy = x[3 * s + 1] - x[3 * d + 1];
        float dz = x[3 * s + 2] - x[3 * d + 2];
        g_sqd[e] = dx * dx + dy * dy + dz * dz;
    }
}

// ---------------------------------------------------------------------------
// pq_kernel: [Ph|Qh] = feat @ [W1a|W1b], HMMA fp16.
// A fragments loaded DIRECTLY global->registers (no smem staging).
// smem (words): sW [128][36]=4608 | sb1 64
// ---------------------------------------------------------------------------
#define PQ_SMEM_WORDS (4608 + 64)
#define PQ_SMEM_BYTES (PQ_SMEM_WORDS * 4)    // 18,688

__global__ __launch_bounds__(256) void pq_kernel(
    const float* __restrict__ feat,
    const float* __restrict__ W1, const float* __restrict__ b1)
{
    extern __shared__ uint32_t ps[];
    uint32_t* sW  = ps;
    float*    sb1 = reinterpret_cast<float*>(ps + 4608);
    const int tid = threadIdx.x;
    const int w   = tid >> 5;
    const int l   = tid & 31;
    const int g   = l >> 2;
    const int l4  = l & 3;

    for (int i = tid; i < 128 * 64; i += 256) {
        int n = i >> 6, k = i & 63;
        float v = (n < 64) ? W1[k * 64 + n] : W1[(64 + k) * 64 + (n - 64)];
        reinterpret_cast<__half*>(sW + n * 36)[kpos(k >> 1) * 2 + (k & 1)] =
            __float2half(v);
    }
    if (tid < 64) sb1[tid] = b1[tid];
    __syncthreads();

    for (int grp = blockIdx.x * 8 + w; grp < NGRP; grp += gridDim.x * 8) {
        const int n0 = grp * 16;
        const float* rg  = feat + (size_t)(n0 + g) * 64;
        const float* rg8 = feat + (size_t)(n0 + g + 8) * 64;

        // A fragments straight from global (16 independent 8B loads)
        uint32_t Aw[16];
        #pragma unroll
        for (int kk = 0; kk < 4; kk++) {
            const int c = kk * 16 + 2 * l4;
            float2 v0 = *reinterpret_cast<const float2*>(rg + c);
            float2 v1 = *reinterpret_cast<const float2*>(rg8 + c);
            float2 v2 = *reinterpret_cast<const float2*>(rg + c + 8);
            float2 v3 = *reinterpret_cast<const float2*>(rg8 + c + 8);
            Aw[kk * 4 + 0] = h2pack(v0.x, v0.y);
            Aw[kk * 4 + 1] = h2pack(v1.x, v1.y);
            Aw[kk * 4 + 2] = h2pack(v2.x, v2.y);
            Aw[kk * 4 + 3] = h2pack(v3.x, v3.y);
        }

        #pragma unroll
        for (int pass = 0; pass < 2; pass++) {
            float acc[8][4];
            #pragma unroll
            for (int ct = 0; ct < 8; ct++)
                acc[ct][0] = acc[ct][1] = acc[ct][2] = acc[ct][3] = 0.f;

            #pragma unroll
            for (int kk = 0; kk < 4; kk++) {
                const int ko = kk * 8 + 2 * l4;
                #pragma unroll
                for (int ct = 0; ct < 8; ct++) {
                    uint2 bv = *reinterpret_cast<const uint2*>(
                        sW + ((pass * 8 + ct) * 8 + g) * 36 + ko);
                    mma16h(acc[ct], Aw[kk*4+0], Aw[kk*4+1],
                           Aw[kk*4+2], Aw[kk*4+3], bv.x, bv.y);
                }
            }

            uint32_t* dstbuf = pass ? g_Qh : g_Ph;
            #pragma unroll
            for (int ct = 0; ct < 8; ct++) {
                const int n = ct * 8 + 2 * l4;
                const float bb0 = pass ? 0.f : sb1[n];
                const float bb1 = pass ? 0.f : sb1[n + 1];
                const int j = ct * 4 + l4;
                dstbuf[(size_t)(n0 + g) * 32 + j] =
                    h2pack(acc[ct][0] + bb0, acc[ct][1] + bb1);
                dstbuf[(size_t)(n0 + g + 8) * 32 + j] =
                    h2pack(acc[ct][2] + bb0, acc[ct][3] + bb1);
            }
        }
    }
}

// ---------------------------------------------------------------------------
// Edge kernel: persistent, 4 CTAs/SM, 64-edge tiles.
//   warps 0-3: consumers — layer-2 HMMA fp16 + gate + full-width red4 scatter
//   warps 4-7: producers — h1 = relu(Ph[src]+Qh[dst]+sqd*wl), pipelined
// smem words: A0 [64][36]=2304 | A1 2304 | W2f [64][36]=2304 | misc
// ---------------------------------------------------------------------------
#define O_A0   0
#define O_A1   2304
#define O_W2F  4608
#define O_WL   6912
#define O_B2   6976
#define O_WE   7040
#define O_BE   7104
#define EDGE_SMEM_WORDS 7112   // 28,448 B static

__global__ __launch_bounds__(256, 4) void edge_kernel(
    const int* __restrict__ src, const int* __restrict__ dst,
    const float* __restrict__ W1, const float* __restrict__ W2,
    const float* __restrict__ b2, const float* __restrict__ we,
    const float* __restrict__ be)
{
    __shared__ float sm[EDGE_SMEM_WORDS];
    const int tid  = threadIdx.x;
    const int wid  = tid >> 5;
    const int lane = tid & 31;

    for (int i = tid; i < 64 * 64; i += 256) {
        int k = i >> 6, n = i & 63;
        __half* rowp = reinterpret_cast<__half*>(
            reinterpret_cast<uint32_t*>(sm) + O_W2F + n * 36);
        rowp[kpos(k >> 1) * 2 + (k & 1)] = __float2half(W2[i]);
    }
    if (tid < 64) {
        sm[O_WL + tid] = W1[128 * 64 + tid];
        sm[O_B2 + tid] = b2[tid];
        sm[O_WE + tid] = we[tid];
    }
    if (tid == 0) sm[O_BE] = be[0];
    __syncthreads();

    // ---------------- producer (software-pipelined, half2 gathers) ----------
    const int pw    = wid - 4;
    const int kposl = kpos(lane);
    auto fill = [&](uint32_t* A, int t) {
        const float2 wl = *reinterpret_cast<const float2*>(sm + O_WL + 2 * lane);
        const int e0 = t * TILE_E + pw * 16;
        int   sI = 0, dI = 0;
        float sqI = 0.f;
        if (lane < 16) {
            sI  = src[e0 + lane];
            dI  = dst[e0 + lane];
            sqI = g_sqd[e0 + lane];
        }
        #pragma unroll
        for (int b = 0; b < 2; b++) {
            uint32_t pv[8], qv[8];
            #pragma unroll
            for (int j = 0; j < 8; j++) {
                const int it = b * 8 + j;
                const int s = __shfl_sync(0xffffffffu, sI, it);
                const int d = __shfl_sync(0xffffffffu, dI, it);
                pv[j] = g_Ph[(size_t)s * 32 + lane];
                qv[j] = g_Qh[(size_t)d * 32 + lane];
            }
            #pragma unroll
            for (int j = 0; j < 8; j++) {
                const int it = b * 8 + j;
                const float sq = __shfl_sync(0xffffffffu, sqI, it);
                float2 p2 = h2unpack(pv[j]);
                float2 q2 = h2unpack(qv[j]);
                float h0 = fmaxf(p2.x + q2.x + sq * wl.x, 0.f);
                float h1 = fmaxf(p2.y + q2.y + sq * wl.y, 0.f);
                A[(pw * 16 + it) * 36 + kposl] = h2pack(h0, h1);
            }
        }
    };

    // ---------------- consumer constants ----------------
    const int g  = lane >> 2;
    const int l4 = lane & 3;
    const int eb = wid * 16;
    const bool even = !(l4 & 1);

    if (wid >= 4) fill(reinterpret_cast<uint32_t*>(sm) + O_A0, blockIdx.x);
    __syncthreads();

    int buf = 0;
    for (int t = blockIdx.x; t < N_TILES; t += EDGE_CTAS) {
        if (wid >= 4) {
            const int tn = t + EDGE_CTAS;
            if (tn < N_TILES)
                fill(reinterpret_cast<uint32_t*>(sm) + (buf ? O_A0 : O_A1), tn);
        } else {
            const uint32_t* Au =
                reinterpret_cast<const uint32_t*>(sm) + (buf ? O_A1 : O_A0);
            const uint32_t* W2u = reinterpret_cast<const uint32_t*>(sm) + O_W2F;

            float acc[8][4];
            #pragma unroll
            for (int ct = 0; ct < 8; ct++)
                acc[ct][0] = acc[ct][1] = acc[ct][2] = acc[ct][3] = 0.f;

            #pragma unroll
            for (int kk = 0; kk < 4; kk++) {
                const int ko = kk * 8 + 2 * l4;
                uint2 alo = *reinterpret_cast<const uint2*>(Au + (eb + g) * 36 + ko);
                uint2 ahi = *reinterpret_cast<const uint2*>(Au + (eb + g + 8) * 36 + ko);
                #pragma unroll
                for (int ct = 0; ct < 8; ct++) {
                    uint2 bv = *reinterpret_cast<const uint2*>(
                        W2u + (ct * 8 + g) * 36 + ko);
                    mma16h(acc[ct], alo.x, ahi.x, alo.y, ahi.y, bv.x, bv.y);
                }
            }

            float pg = 0.f, pg8 = 0.f;
            #pragma unroll
            for (int ct = 0; ct < 8; ct++) {
                const int c0 = ct * 8 + 2 * l4;
                const float bb0 = sm[O_B2 + c0], bb1 = sm[O_B2 + c0 + 1];
                const float w0 = sm[O_WE + c0],  w1 = sm[O_WE + c0 + 1];
                acc[ct][0] = fmaxf(acc[ct][0] + bb0, 0.f);
                acc[ct][1] = fmaxf(acc[ct][1] + bb1, 0.f);
                acc[ct][2] = fmaxf(acc[ct][2] + bb0, 0.f);
                acc[ct][3] = fmaxf(acc[ct][3] + bb1, 0.f);
                pg  = fmaf(acc[ct][0], w0, fmaf(acc[ct][1], w1, pg));
                pg8 = fmaf(acc[ct][2], w0, fmaf(acc[ct][3], w1, pg8));
            }
            pg  += __shfl_xor_sync(0xffffffffu, pg, 1);
            pg  += __shfl_xor_sync(0xffffffffu, pg, 2);
            pg8 += __shfl_xor_sync(0xffffffffu, pg8, 1);
            pg8 += __shfl_xor_sync(0xffffffffu, pg8, 2);
            const float be0 = sm[O_BE];
            const float G  = 1.f / (1.f + __expf(-(pg + be0)));
            const float G8 = 1.f / (1.f + __expf(-(pg8 + be0)));

            const int dg  = dst[t * TILE_E + eb + g];
            const int dg8 = dst[t * TILE_E + eb + g + 8];
            float* bp  = g_msum + (size_t)dg * 64;
            float* bp8 = g_msum + (size_t)dg8 * 64;
            #pragma unroll
            for (int a = 0; a < 4; a++) {
                const int ct0 = 2 * a, ct1 = 2 * a + 1;
                float s00 = acc[ct0][0] * G,  s01 = acc[ct0][1] * G;
                float s02 = acc[ct0][2] * G8, s03 = acc[ct0][3] * G8;
                float s10 = acc[ct1][0] * G,  s11 = acc[ct1][1] * G;
                float s12 = acc[ct1][2] * G8, s13 = acc[ct1][3] * G8;
                float x0 = __shfl_xor_sync(0xffffffffu, s00, 1);
                float x1 = __shfl_xor_sync(0xffffffffu, s01, 1);
                float x2 = __shfl_xor_sync(0xffffffffu, s02, 1);
                float x3 = __shfl_xor_sync(0xffffffffu, s03, 1);
                float y0 = __shfl_xor_sync(0xffffffffu, s10, 1);
                float y1 = __shfl_xor_sync(0xffffffffu, s11, 1);
                float y2 = __shfl_xor_sync(0xffffffffu, s12, 1);
                float y3 = __shfl_xor_sync(0xffffffffu, s13, 1);
                const int chb = (even ? ct0 : ct1) * 8 + 2 * (l4 & ~1);
                float a0 = even ? s00 : y0,  a1 = even ? s01 : y1;
                float a2 = even ? x0  : s10, a3 = even ? x1  : s11;
                float b0 = even ? s02 : y2,  b1 = even ? s03 : y3;
                float b2 = even ? x2  : s12, b3 = even ? x3  : s13;
                red4(bp + chb,  a0, a1, a2, a3);
                red4(bp8 + chb, b0, b1, b2, b3);
            }
        }
        __syncthreads();
        buf ^= 1;
    }
}

// ---------------------------------------------------------------------------
// node_kernel: HMMA fp16; layer-1 A direct from global (msum+feat in regs),
// H staged per-warp for layer 2.
// smem words: sU1h 2304 | sU2h 2304 | c1 64 | c2 64 | per-warp H 576 x 8
// ---------------------------------------------------------------------------
#define NODE_SMEM_WORDS (2304 + 2304 + 64 + 64 + 8 * 576)
#define NODE_SMEM_BYTES (NODE_SMEM_WORDS * 4)   // 37,376

__global__ __launch_bounds__(256, 4) void node_kernel(
    const float* __restrict__ feat,
    const float* __restrict__ U1, const float* __restrict__ c1,
    const float* __restrict__ U2, const float* __restrict__ c2,
    float* __restrict__ out)
{
    extern __shared__ uint32_t ns[];
    uint32_t* sU1h = ns;
    uint32_t* sU2h = ns + 2304;
    float*    sc1  = reinterpret_cast<float*>(ns + 4608);
    float*    sc2  = reinterpret_cast<float*>(ns + 4672);
    const int tid = threadIdx.x;
    const int w   = tid >> 5;
    const int l   = tid & 31;
    const int g   = l >> 2;
    const int l4  = l & 3;
    uint32_t* pH = ns + 4736 + w * 576;

    for (int i = tid; i < 64 * 64; i += 256) {
        int k = i >> 6, n = i & 63;
        reinterpret_cast<__half*>(sU1h + n * 36)[kpos(k >> 1) * 2 + (k & 1)] =
            __float2half(U1[i]);
        reinterpret_cast<__half*>(sU2h + n * 36)[kpos(k >> 1) * 2 + (k & 1)] =
            __float2half(U2[i]);
    }
    if (tid < 64) { sc1[tid] = c1[tid]; sc2[tid] = c2[tid]; }
    __syncthreads();

    for (int grp = blockIdx.x * 8 + w; grp < NGRP; grp += gridDim.x * 8) {
        const int n0 = grp * 16;
        const float* fg  = feat + (size_t)(n0 + g) * 64;
        const float* fg8 = feat + (size_t)(n0 + g + 8) * 64;
        const float* mg  = g_msum + (size_t)(n0 + g) * 64;
        const float* mg8 = g_msum + (size_t)(n0 + g + 8) * 64;

        // layer-1 A fragments direct from global: (msum + feat) packed half2
        uint32_t Aw[16];
        #pragma unroll
        for (int kk = 0; kk < 4; kk++) {
            const int c = kk * 16 + 2 * l4;
            float2 f0 = *reinterpret_cast<const float2*>(fg + c);
            float2 m0 = *reinterpret_cast<const float2*>(mg + c);
            float2 f1 = *reinterpret_cast<const float2*>(fg8 + c);
            float2 m1 = *reinterpret_cast<const float2*>(mg8 + c);
            float2 f2 = *reinterpret_cast<const float2*>(fg + c + 8);
            float2 m2 = *reinterpret_cast<const float2*>(mg + c + 8);
            float2 f3 = *reinterpret_cast<const float2*>(fg8 + c + 8);
            float2 m3 = *reinterpret_cast<const float2*>(mg8 + c + 8);
            Aw[kk * 4 + 0] = h2pack(f0.x + m0.x, f0.y + m0.y);
            Aw[kk * 4 + 1] = h2pack(f1.x + m1.x, f1.y + m1.y);
            Aw[kk * 4 + 2] = h2pack(f2.x + m2.x, f2.y + m2.y);
            Aw[kk * 4 + 3] = h2pack(f3.x + m3.x, f3.y + m3.y);
        }

        // layer 1
        float acc[8][4];
        #pragma unroll
        for (int ct = 0; ct < 8; ct++)
            acc[ct][0] = acc[ct][1] = acc[ct][2] = acc[ct][3] = 0.f;
        #pragma unroll
        for (int kk = 0; kk < 4; kk++) {
            #pragma unroll
            for (int ct = 0; ct < 8; ct++) {
                uint2 bv = *reinterpret_cast<const uint2*>(
                    sU1h + (ct * 8 + g) * 36 + kk * 8 + 2 * l4);
                mma16h(acc[ct], Aw[kk*4+0], Aw[kk*4+1],
                       Aw[kk*4+2], Aw[kk*4+3], bv.x, bv.y);
            }
        }
        // epilogue 1: relu -> H staged in smem
        #pragma unroll
        for (int ct = 0; ct < 8; ct++) {
            const int c0 = ct * 8 + 2 * l4;
            const int j  = ct * 4 + l4;
            const float bb0 = sc1[c0], bb1 = sc1[c0 + 1];
            pH[g * 36 + kpos(j)] =
                h2pack(fmaxf(acc[ct][0] + bb0, 0.f), fmaxf(acc[ct][1] + bb1, 0.f));
            pH[(g + 8) * 36 + kpos(j)] =
                h2pack(fmaxf(acc[ct][2] + bb0, 0.f), fmaxf(acc[ct][3] + bb1, 0.f));
        }
        __syncwarp();

        // layer 2
        #pragma unroll
        for (int ct = 0; ct < 8; ct++)
            acc[ct][0] = acc[ct][1] = acc[ct][2] = acc[ct][3] = 0.f;
        #pragma unroll
        for (int kk = 0; kk < 4; kk++) {
            const int ko = kk * 8 + 2 * l4;
            uint2 alo = *reinterpret_cast<const uint2*>(pH + g * 36 + ko);
            uint2 ahi = *reinterpret_cast<const uint2*>(pH + (g + 8) * 36 + ko);
            #pragma unroll
            for (int ct = 0; ct < 8; ct++) {
                uint2 bv = *reinterpret_cast<const uint2*>(
                    sU2h + (ct * 8 + g) * 36 + ko);
                mma16h(acc[ct], alo.x, ahi.x, alo.y, ahi.y, bv.x, bv.y);
            }
        }
        // epilogue 2: + c2 + feat residual (fp32 out)
        #pragma unroll
        for (int ct = 0; ct < 8; ct++) {
            const int c0 = ct * 8 + 2 * l4;
            const float bb0 = sc2[c0], bb1 = sc2[c0 + 1];
            float2 f0 = *reinterpret_cast<const float2*>(fg + c0);
            float2 f1 = *reinterpret_cast<const float2*>(fg8 + c0);
            *reinterpret_cast<float2*>(out + (size_t)(n0 + g) * 64 + c0) =
                make_float2(acc[ct][0] + bb0 + f0.x, acc[ct][1] + bb1 + f0.y);
            *reinterpret_cast<float2*>(out + (size_t)(n0 + g + 8) * 64 + c0) =
                make_float2(acc[ct][2] + bb0 + f1.x, acc[ct][3] + bb1 + f1.y);
        }
        __syncwarp();
    }
}

// ---------------------------------------------------------------------------
extern "C" void kernel_launch(void* const* d_in, const int* in_sizes, int n_in,
                              void* d_out, int out_size)
{
    const float* feat = (const float*)d_in[0];
    const float* x    = (const float*)d_in[1];
    const int*   src  = (const int*)  d_in[2];
    const int*   dst  = (const int*)  d_in[3];
    const float* W1   = (const float*)d_in[4];
    const float* b1   = (const float*)d_in[5];
    const float* W2   = (const float*)d_in[6];
    const float* b2   = (const float*)d_in[7];
    const float* we   = (const float*)d_in[8];
    const float* be   = (const float*)d_in[9];
    const float* U1   = (const float*)d_in[10];
    const float* c1   = (const float*)d_in[11];
    const float* U2   = (const float*)d_in[12];
    const float* c2   = (const float*)d_in[13];
    float* out = (float*)d_out;

    cudaFuncSetAttribute(pq_kernel,
                         cudaFuncAttributeMaxDynamicSharedMemorySize,
                         PQ_SMEM_BYTES);
    cudaFuncSetAttribute(node_kernel,
                         cudaFuncAttributeMaxDynamicSharedMemorySize,
                         NODE_SMEM_BYTES);

    zs_kernel<<<1184, 256>>>(x, src, dst);
    pq_kernel<<<391, 256, PQ_SMEM_BYTES>>>(feat, W1, b1);
    edge_kernel<<<EDGE_CTAS, 256>>>(src, dst, W1, W2, b2, we, be);
    node_kernel<<<592, 256, NODE_SMEM_BYTES>>>(feat, U1, c1, U2, c2, out);
}

// round 14
// speedup vs baseline: 1.0814x; 1.0814x over previous
#include <cuda_runtime.h>
#include <cuda_fp16.h>
#include <math.h>
#include <cstdint>

#define N_NODES 50000
#define N_EDGES 800000
#define N_CHUNK (N_EDGES / 16)       // 50000 16-edge chunks
#define EDGE_CTAS 444                // 3 per SM
#define NGRP    (N_NODES / 16)       // 3125 exact

// Device scratch (no allocs allowed).
__device__ float    g_msum[N_NODES * 64];
__device__ uint32_t g_Ph[N_NODES * 32];   // half2: feat@W1a + b1
__device__ uint32_t g_Qh[N_NODES * 32];   // half2: feat@W1b

// fragment permutation within each 8-slot group
__host__ __device__ __forceinline__ int kpos(int s) {
    return (s & ~7) + 2 * (s & 3) + ((s >> 2) & 1);
}
__device__ __forceinline__ void mma16h(float d[4], uint32_t a0, uint32_t a1,
                                       uint32_t a2, uint32_t a3,
                                       uint32_t b0, uint32_t b1) {
    asm("mma.sync.aligned.m16n8k16.row.col.f32.f16.f16.f32 "
        "{%0,%1,%2,%3}, {%4,%5,%6,%7}, {%8,%9}, {%0,%1,%2,%3};"
        : "+f"(d[0]), "+f"(d[1]), "+f"(d[2]), "+f"(d[3])
        : "r"(a0), "r"(a1), "r"(a2), "r"(a3), "r"(b0), "r"(b1));
}
__device__ __forceinline__ void red4(float* p, float a, float b, float c, float d) {
    asm volatile("red.global.add.v4.f32 [%0], {%1,%2,%3,%4};"
                 :: "l"(p), "f"(a), "f"(b), "f"(c), "f"(d) : "memory");
}
__device__ __forceinline__ uint32_t h2pack(float a, float b) {
    __half2 hv = __floats2half2_rn(a, b);
    return *reinterpret_cast<uint32_t*>(&hv);
}
__device__ __forceinline__ float2 h2unpack(uint32_t u) {
    return __half22float2(*reinterpret_cast<__half2*>(&u));
}
// store 4 consecutive-n halves of weight row k into f16 B layout
__device__ __forceinline__ void wstore4(uint32_t* sWbase, int n0, int k, float4 v) {
    const int hidx = kpos(k >> 1) * 2 + (k & 1);
    reinterpret_cast<__half*>(sWbase + (n0 + 0) * 36)[hidx] = __float2half(v.x);
    reinterpret_cast<__half*>(sWbase + (n0 + 1) * 36)[hidx] = __float2half(v.y);
    reinterpret_cast<__half*>(sWbase + (n0 + 2) * 36)[hidx] = __float2half(v.z);
    reinterpret_cast<__half*>(sWbase + (n0 + 3) * 36)[hidx] = __float2half(v.w);
}

// ---------------------------------------------------------------------------
// zero_kernel: zero the scatter accumulator
// ---------------------------------------------------------------------------
__global__ __launch_bounds__(256) void zero_kernel() {
    int i = blockIdx.x * 256 + threadIdx.x;
    if (i < N_NODES * 16)
        reinterpret_cast<float4*>(g_msum)[i] = make_float4(0.f, 0.f, 0.f, 0.f);
}

// ---------------------------------------------------------------------------
// pq_kernel: [Ph|Qh] = feat @ [W1a|W1b], HMMA fp16, A direct from global.
// smem (words): sW [128][36]=4608 | sb1 64
// ---------------------------------------------------------------------------
#define PQ_SMEM_WORDS (4608 + 64)
#define PQ_SMEM_BYTES (PQ_SMEM_WORDS * 4)    // 18,688

__global__ __launch_bounds__(256) void pq_kernel(
    const float* __restrict__ feat,
    const float* __restrict__ W1, const float* __restrict__ b1)
{
    extern __shared__ uint32_t ps[];
    uint32_t* sW  = ps;
    float*    sb1 = reinterpret_cast<float*>(ps + 4608);
    const int tid = threadIdx.x;
    const int w   = tid >> 5;
    const int l   = tid & 31;
    const int g   = l >> 2;
    const int l4  = l & 3;

    // vectorized weight preload: W1a rows 0..63 of B, W1b rows 64..127
    const float4* W1v = reinterpret_cast<const float4*>(W1);
    for (int i = tid; i < 1024; i += 256) {
        const int k = i >> 4, n0 = (i & 15) * 4;
        wstore4(sW, n0, k, W1v[i]);               // W1[k][n0..] -> rows n0..
        wstore4(sW + 64 * 36, n0, k, W1v[1024 + i]); // W1[64+k][n0..]
    }
    if (tid < 64) sb1[tid] = b1[tid];
    __syncthreads();

    for (int grp = blockIdx.x * 8 + w; grp < NGRP; grp += gridDim.x * 8) {
        const int n0 = grp * 16;
        const float* rg  = feat + (size_t)(n0 + g) * 64;
        const float* rg8 = feat + (size_t)(n0 + g + 8) * 64;

        uint32_t Aw[16];
        #pragma unroll
        for (int kk = 0; kk < 4; kk++) {
            const int c = kk * 16 + 2 * l4;
            float2 v0 = *reinterpret_cast<const float2*>(rg + c);
            float2 v1 = *reinterpret_cast<const float2*>(rg8 + c);
            float2 v2 = *reinterpret_cast<const float2*>(rg + c + 8);
            float2 v3 = *reinterpret_cast<const float2*>(rg8 + c + 8);
            Aw[kk * 4 + 0] = h2pack(v0.x, v0.y);
            Aw[kk * 4 + 1] = h2pack(v1.x, v1.y);
            Aw[kk * 4 + 2] = h2pack(v2.x, v2.y);
            Aw[kk * 4 + 3] = h2pack(v3.x, v3.y);
        }

        #pragma unroll
        for (int pass = 0; pass < 2; pass++) {
            float acc[8][4];
            #pragma unroll
            for (int ct = 0; ct < 8; ct++)
                acc[ct][0] = acc[ct][1] = acc[ct][2] = acc[ct][3] = 0.f;

            #pragma unroll
            for (int kk = 0; kk < 4; kk++) {
                const int ko = kk * 8 + 2 * l4;
                #pragma unroll
                for (int ct = 0; ct < 8; ct++) {
                    uint2 bv = *reinterpret_cast<const uint2*>(
                        sW + ((pass * 8 + ct) * 8 + g) * 36 + ko);
                    mma16h(acc[ct], Aw[kk*4+0], Aw[kk*4+1],
                           Aw[kk*4+2], Aw[kk*4+3], bv.x, bv.y);
                }
            }

            uint32_t* dstbuf = pass ? g_Qh : g_Ph;
            #pragma unroll
            for (int ct = 0; ct < 8; ct++) {
                const int n = ct * 8 + 2 * l4;
                const float bb0 = pass ? 0.f : sb1[n];
                const float bb1 = pass ? 0.f : sb1[n + 1];
                const int j = ct * 4 + l4;
                dstbuf[(size_t)(n0 + g) * 32 + j] =
                    h2pack(acc[ct][0] + bb0, acc[ct][1] + bb1);
                dstbuf[(size_t)(n0 + g + 8) * 32 + j] =
                    h2pack(acc[ct][2] + bb0, acc[ct][3] + bb1);
            }
        }
    }
}

// ---------------------------------------------------------------------------
// Edge kernel: every warp owns 16-edge chunks end-to-end. No CTA-level sync
// in the loop; warp-private A buffers; sqd computed inline.
// smem words: W2f 2304 | A[8][576]=4608 | wl 64 | b2 64 | we 64 | be 8
// ---------------------------------------------------------------------------
#define O_W2F  0
#define O_A    2304
#define O_WL   6912
#define O_B2   6976
#define O_WE   7040
#define O_BE   7104
#define EDGE_SMEM_WORDS 7112   // 28,448 B static

__global__ __launch_bounds__(256, 3) void edge_kernel(
    const int* __restrict__ src, const int* __restrict__ dst,
    const float* __restrict__ x,
    const float* __restrict__ W1, const float* __restrict__ W2,
    const float* __restrict__ b2, const float* __restrict__ we,
    const float* __restrict__ be)
{
    __shared__ uint32_t sm[EDGE_SMEM_WORDS];
    float* smf = reinterpret_cast<float*>(sm);
    const int tid  = threadIdx.x;
    const int wid  = tid >> 5;
    const int lane = tid & 31;

    // vectorized W2 preload into f16 B layout
    const float4* W2v = reinterpret_cast<const float4*>(W2);
    for (int i = tid; i < 1024; i += 256) {
        const int k = i >> 4, n0 = (i & 15) * 4;
        wstore4(sm + O_W2F, n0, k, W2v[i]);
    }
    if (tid < 64) {
        smf[O_WL + tid] = W1[128 * 64 + tid];
        smf[O_B2 + tid] = b2[tid];
        smf[O_WE + tid] = we[tid];
    }
    if (tid == 0) smf[O_BE] = be[0];
    __syncthreads();

    const int g  = lane >> 2;
    const int l4 = lane & 3;
    const bool even = !(l4 & 1);
    const int kposl = kpos(lane);
    const float wlx = smf[O_WL + 2 * lane];
    const float wly = smf[O_WL + 2 * lane + 1];
    const float be0 = smf[O_BE];
    uint32_t* Aw = sm + O_A + wid * 576;
    const uint32_t* W2u = sm + O_W2F;

    for (int c = blockIdx.x * 8 + wid; c < N_CHUNK; c += gridDim.x * 8) {
        const int e0 = c * 16;

        // ---- per-edge metadata + inline sqd (lanes 0..15) ----
        int sI = 0, dI = 0;
        float sqI = 0.f;
        if (lane < 16) {
            sI = src[e0 + lane];
            dI = dst[e0 + lane];
            float ax = x[3 * sI], ay = x[3 * sI + 1], az = x[3 * sI + 2];
            float bx = x[3 * dI], by = x[3 * dI + 1], bz = x[3 * dI + 2];
            float dx = ax - bx, dy = ay - by, dz = az - bz;
            sqI = dx * dx + dy * dy + dz * dz;
        }

        // ---- gather + h1 -> warp-private A ----
        #pragma unroll
        for (int b = 0; b < 2; b++) {
            uint32_t pv[8], qv[8];
            #pragma unroll
            for (int j = 0; j < 8; j++) {
                const int it = b * 8 + j;
                const int s = __shfl_sync(0xffffffffu, sI, it);
                const int d = __shfl_sync(0xffffffffu, dI, it);
                pv[j] = g_Ph[(size_t)s * 32 + lane];
                qv[j] = g_Qh[(size_t)d * 32 + lane];
            }
            #pragma unroll
            for (int j = 0; j < 8; j++) {
                const int it = b * 8 + j;
                const float sq = __shfl_sync(0xffffffffu, sqI, it);
                float2 p2 = h2unpack(pv[j]);
                float2 q2 = h2unpack(qv[j]);
                float h0 = fmaxf(p2.x + q2.x + sq * wlx, 0.f);
                float h1 = fmaxf(p2.y + q2.y + sq * wly, 0.f);
                Aw[it * 36 + kposl] = h2pack(h0, h1);
            }
        }
        __syncwarp();

        // ---- layer 2: 32 HMMA on own 16 edges ----
        float acc[8][4];
        #pragma unroll
        for (int ct = 0; ct < 8; ct++)
            acc[ct][0] = acc[ct][1] = acc[ct][2] = acc[ct][3] = 0.f;

        #pragma unroll
        for (int kk = 0; kk < 4; kk++) {
            const int ko = kk * 8 + 2 * l4;
            uint2 alo = *reinterpret_cast<const uint2*>(Aw + g * 36 + ko);
            uint2 ahi = *reinterpret_cast<const uint2*>(Aw + (g + 8) * 36 + ko);
            #pragma unroll
            for (int ct = 0; ct < 8; ct++) {
                uint2 bv = *reinterpret_cast<const uint2*>(
                    W2u + (ct * 8 + g) * 36 + ko);
                mma16h(acc[ct], alo.x, ahi.x, alo.y, ahi.y, bv.x, bv.y);
            }
        }

        // ---- epilogue: m = relu(d2+b2), gate ----
        float pg = 0.f, pg8 = 0.f;
        #pragma unroll
        for (int ct = 0; ct < 8; ct++) {
            const int c0 = ct * 8 + 2 * l4;
            const float bb0 = smf[O_B2 + c0], bb1 = smf[O_B2 + c0 + 1];
            const float w0 = smf[O_WE + c0],  w1 = smf[O_WE + c0 + 1];
            acc[ct][0] = fmaxf(acc[ct][0] + bb0, 0.f);
            acc[ct][1] = fmaxf(acc[ct][1] + bb1, 0.f);
            acc[ct][2] = fmaxf(acc[ct][2] + bb0, 0.f);
            acc[ct][3] = fmaxf(acc[ct][3] + bb1, 0.f);
            pg  = fmaf(acc[ct][0], w0, fmaf(acc[ct][1], w1, pg));
            pg8 = fmaf(acc[ct][2], w0, fmaf(acc[ct][3], w1, pg8));
        }
        pg  += __shfl_xor_sync(0xffffffffu, pg, 1);
        pg  += __shfl_xor_sync(0xffffffffu, pg, 2);
        pg8 += __shfl_xor_sync(0xffffffffu, pg8, 1);
        pg8 += __shfl_xor_sync(0xffffffffu, pg8, 2);
        const float G  = 1.f / (1.f + __expf(-(pg + be0)));
        const float G8 = 1.f / (1.f + __expf(-(pg8 + be0)));

        // ---- scatter: dst via shfl, ct-pairs -> full-width red4 ----
        const int dg  = __shfl_sync(0xffffffffu, dI, g);
        const int dg8 = __shfl_sync(0xffffffffu, dI, g + 8);
        float* bp  = g_msum + (size_t)dg * 64;
        float* bp8 = g_msum + (size_t)dg8 * 64;
        #pragma unroll
        for (int a = 0; a < 4; a++) {
            const int ct0 = 2 * a, ct1 = 2 * a + 1;
            float s00 = acc[ct0][0] * G,  s01 = acc[ct0][1] * G;
            float s02 = acc[ct0][2] * G8, s03 = acc[ct0][3] * G8;
            float s10 = acc[ct1][0] * G,  s11 = acc[ct1][1] * G;
            float s12 = acc[ct1][2] * G8, s13 = acc[ct1][3] * G8;
            float x0 = __shfl_xor_sync(0xffffffffu, s00, 1);
            float x1 = __shfl_xor_sync(0xffffffffu, s01, 1);
            float x2 = __shfl_xor_sync(0xffffffffu, s02, 1);
            float x3 = __shfl_xor_sync(0xffffffffu, s03, 1);
            float y0 = __shfl_xor_sync(0xffffffffu, s10, 1);
            float y1 = __shfl_xor_sync(0xffffffffu, s11, 1);
            float y2 = __shfl_xor_sync(0xffffffffu, s12, 1);
            float y3 = __shfl_xor_sync(0xffffffffu, s13, 1);
            const int chb = (even ? ct0 : ct1) * 8 + 2 * (l4 & ~1);
            float a0 = even ? s00 : y0,  a1 = even ? s01 : y1;
            float a2 = even ? x0  : s10, a3 = even ? x1  : s11;
            float b0 = even ? s02 : y2,  b1 = even ? s03 : y3;
            float b2 = even ? x2  : s12, b3 = even ? x3  : s13;
            red4(bp + chb,  a0, a1, a2, a3);
            red4(bp8 + chb, b0, b1, b2, b3);
        }
        __syncwarp();   // A reuse next chunk
    }
}

// ---------------------------------------------------------------------------
// node_kernel: HMMA fp16; layer-1 A direct from global; H staged per-warp.
// smem words: sU1h 2304 | sU2h 2304 | c1 64 | c2 64 | per-warp H 576 x 8
// ---------------------------------------------------------------------------
#define NODE_SMEM_WORDS (2304 + 2304 + 64 + 64 + 8 * 576)
#define NODE_SMEM_BYTES (NODE_SMEM_WORDS * 4)   // 37,376

__global__ __launch_bounds__(256, 4) void node_kernel(
    const float* __restrict__ feat,
    const float* __restrict__ U1, const float* __restrict__ c1,
    const float* __restrict__ U2, const float* __restrict__ c2,
    float* __restrict__ out)
{
    extern __shared__ uint32_t ns[];
    uint32_t* sU1h = ns;
    uint32_t* sU2h = ns + 2304;
    float*    sc1  = reinterpret_cast<float*>(ns + 4608);
    float*    sc2  = reinterpret_cast<float*>(ns + 4672);
    const int tid = threadIdx.x;
    const int w   = tid >> 5;
    const int l   = tid & 31;
    const int g   = l >> 2;
    const int l4  = l & 3;
    uint32_t* pH = ns + 4736 + w * 576;

    // vectorized weight preload
    const float4* U1v = reinterpret_cast<const float4*>(U1);
    const float4* U2v = reinterpret_cast<const float4*>(U2);
    for (int i = tid; i < 1024; i += 256) {
        const int k = i >> 4, n0 = (i & 15) * 4;
        wstore4(sU1h, n0, k, U1v[i]);
        wstore4(sU2h, n0, k, U2v[i]);
    }
    if (tid < 64) { sc1[tid] = c1[tid]; sc2[tid] = c2[tid]; }
    __syncthreads();

    for (int grp = blockIdx.x * 8 + w; grp < NGRP; grp += gridDim.x * 8) {
        const int n0 = grp * 16;
        const float* fg  = feat + (size_t)(n0 + g) * 64;
        const float* fg8 = feat + (size_t)(n0 + g + 8) * 64;
        const float* mg  = g_msum + (size_t)(n0 + g) * 64;
        const float* mg8 = g_msum + (size_t)(n0 + g + 8) * 64;

        uint32_t Aw[16];
        #pragma unroll
        for (int kk = 0; kk < 4; kk++) {
            const int c = kk * 16 + 2 * l4;
            float2 f0 = *reinterpret_cast<const float2*>(fg + c);
            float2 m0 = *reinterpret_cast<const float2*>(mg + c);
            float2 f1 = *reinterpret_cast<const float2*>(fg8 + c);
            float2 m1 = *reinterpret_cast<const float2*>(mg8 + c);
            float2 f2 = *reinterpret_cast<const float2*>(fg + c + 8);
            float2 m2 = *reinterpret_cast<const float2*>(mg + c + 8);
            float2 f3 = *reinterpret_cast<const float2*>(fg8 + c + 8);
            float2 m3 = *reinterpret_cast<const float2*>(mg8 + c + 8);
            Aw[kk * 4 + 0] = h2pack(f0.x + m0.x, f0.y + m0.y);
            Aw[kk * 4 + 1] = h2pack(f1.x + m1.x, f1.y + m1.y);
            Aw[kk * 4 + 2] = h2pack(f2.x + m2.x, f2.y + m2.y);
            Aw[kk * 4 + 3] = h2pack(f3.x + m3.x, f3.y + m3.y);
        }

        float acc[8][4];
        #pragma unroll
        for (int ct = 0; ct < 8; ct++)
            acc[ct][0] = acc[ct][1] = acc[ct][2] = acc[ct][3] = 0.f;
        #pragma unroll
        for (int kk = 0; kk < 4; kk++) {
            #pragma unroll
            for (int ct = 0; ct < 8; ct++) {
                uint2 bv = *reinterpret_cast<const uint2*>(
                    sU1h + (ct * 8 + g) * 36 + kk * 8 + 2 * l4);
                mma16h(acc[ct], Aw[kk*4+0], Aw[kk*4+1],
                       Aw[kk*4+2], Aw[kk*4+3], bv.x, bv.y);
            }
        }
        // epilogue 1: relu -> H staged in smem
        #pragma unroll
        for (int ct = 0; ct < 8; ct++) {
            const int c0 = ct * 8 + 2 * l4;
            const int j  = ct * 4 + l4;
            const float bb0 = sc1[c0], bb1 = sc1[c0 + 1];
            pH[g * 36 + kpos(j)] =
                h2pack(fmaxf(acc[ct][0] + bb0, 0.f), fmaxf(acc[ct][1] + bb1, 0.f));
            pH[(g + 8) * 36 + kpos(j)] =
                h2pack(fmaxf(acc[ct][2] + bb0, 0.f), fmaxf(acc[ct][3] + bb1, 0.f));
        }
        __syncwarp();

        // layer 2
        #pragma unroll
        for (int ct = 0; ct < 8; ct++)
            acc[ct][0] = acc[ct][1] = acc[ct][2] = acc[ct][3] = 0.f;
        #pragma unroll
        for (int kk = 0; kk < 4; kk++) {
            const int ko = kk * 8 + 2 * l4;
            uint2 alo = *reinterpret_cast<const uint2*>(pH + g * 36 + ko);
            uint2 ahi = *reinterpret_cast<const uint2*>(pH + (g + 8) * 36 + ko);
            #pragma unroll
            for (int ct = 0; ct < 8; ct++) {
                uint2 bv = *reinterpret_cast<const uint2*>(
                    sU2h + (ct * 8 + g) * 36 + ko);
                mma16h(acc[ct], alo.x, ahi.x, alo.y, ahi.y, bv.x, bv.y);
            }
        }
        // epilogue 2: + c2 + feat residual (fp32 out)
        #pragma unroll
        for (int ct = 0; ct < 8; ct++) {
            const int c0 = ct * 8 + 2 * l4;
            const float bb0 = sc2[c0], bb1 = sc2[c0 + 1];
            float2 f0 = *reinterpret_cast<const float2*>(fg + c0);
            float2 f1 = *reinterpret_cast<const float2*>(fg8 + c0);
            *reinterpret_cast<float2*>(out + (size_t)(n0 + g) * 64 + c0) =
                make_float2(acc[ct][0] + bb0 + f0.x, acc[ct][1] + bb1 + f0.y);
            *reinterpret_cast<float2*>(out + (size_t)(n0 + g + 8) * 64 + c0) =
                make_float2(acc[ct][2] + bb0 + f1.x, acc[ct][3] + bb1 + f1.y);
        }
        __syncwarp();
    }
}

// ---------------------------------------------------------------------------
extern "C" void kernel_launch(void* const* d_in, const int* in_sizes, int n_in,
                              void* d_out, int out_size)
{
    const float* feat = (const float*)d_in[0];
    const float* x    = (const float*)d_in[1];
    const int*   src  = (const int*)  d_in[2];
    const int*   dst  = (const int*)  d_in[3];
    const float* W1   = (const float*)d_in[4];
    const float* b1   = (const float*)d_in[5];
    const float* W2   = (const float*)d_in[6];
    const float* b2   = (const float*)d_in[7];
    const float* we   = (const float*)d_in[8];
    const float* be   = (const float*)d_in[9];
    const float* U1   = (const float*)d_in[10];
    const float* c1   = (const float*)d_in[11];
    const float* U2   = (const float*)d_in[12];
    const float* c2   = (const float*)d_in[13];
    float* out = (float*)d_out;

    cudaFuncSetAttribute(pq_kernel,
                         cudaFuncAttributeMaxDynamicSharedMemorySize,
                         PQ_SMEM_BYTES);
    cudaFuncSetAttribute(node_kernel,
                         cudaFuncAttributeMaxDynamicSharedMemorySize,
                         NODE_SMEM_BYTES);

    zero_kernel<<<(N_NODES * 16 + 255) / 256, 256>>>();
    pq_kernel<<<391, 256, PQ_SMEM_BYTES>>>(feat, W1, b1);
    edge_kernel<<<EDGE_CTAS, 256>>>(src, dst, x, W1, W2, b2, we, be);
    node_kernel<<<592, 256, NODE_SMEM_BYTES>>>(feat, U1, c1, U2, c2, out);
}

// round 15
// speedup vs baseline: 1.0932x; 1.0109x over previous
#include <cuda_runtime.h>
#include <cuda_fp16.h>
#include <math.h>
#include <cstdint>

#define N_NODES 50000
#define N_EDGES 800000
#define N_CHUNK (N_EDGES / 16)       // 50000 16-edge chunks
#define EDGE_CTAS 444                // 3 per SM
#define NGRP    (N_NODES / 16)       // 3125 exact

// Device scratch (no allocs allowed).
__device__ float    g_msum[N_NODES * 64];
__device__ uint32_t g_Ph[N_NODES * 32];   // half2: feat@W1a + b1
__device__ uint32_t g_Qh[N_NODES * 32];   // half2: feat@W1b

// fragment permutation within each 8-slot group
__host__ __device__ __forceinline__ int kpos(int s) {
    return (s & ~7) + 2 * (s & 3) + ((s >> 2) & 1);
}
__device__ __forceinline__ void mma16h(float d[4], uint32_t a0, uint32_t a1,
                                       uint32_t a2, uint32_t a3,
                                       uint32_t b0, uint32_t b1) {
    asm("mma.sync.aligned.m16n8k16.row.col.f32.f16.f16.f32 "
        "{%0,%1,%2,%3}, {%4,%5,%6,%7}, {%8,%9}, {%0,%1,%2,%3};"
        : "+f"(d[0]), "+f"(d[1]), "+f"(d[2]), "+f"(d[3])
        : "r"(a0), "r"(a1), "r"(a2), "r"(a3), "r"(b0), "r"(b1));
}
__device__ __forceinline__ void red4(float* p, float a, float b, float c, float d) {
    asm volatile("red.global.add.v4.f32 [%0], {%1,%2,%3,%4};"
                 :: "l"(p), "f"(a), "f"(b), "f"(c), "f"(d) : "memory");
}
__device__ __forceinline__ uint32_t h2pack(float a, float b) {
    __half2 hv = __floats2half2_rn(a, b);
    return *reinterpret_cast<uint32_t*>(&hv);
}
__device__ __forceinline__ float2 h2unpack(uint32_t u) {
    return __half22float2(*reinterpret_cast<__half2*>(&u));
}
// store 4 consecutive-n halves of weight row k into f16 B layout
__device__ __forceinline__ void wstore4(uint32_t* sWbase, int n0, int k, float4 v) {
    const int hidx = kpos(k >> 1) * 2 + (k & 1);
    reinterpret_cast<__half*>(sWbase + (n0 + 0) * 36)[hidx] = __float2half(v.x);
    reinterpret_cast<__half*>(sWbase + (n0 + 1) * 36)[hidx] = __float2half(v.y);
    reinterpret_cast<__half*>(sWbase + (n0 + 2) * 36)[hidx] = __float2half(v.z);
    reinterpret_cast<__half*>(sWbase + (n0 + 3) * 36)[hidx] = __float2half(v.w);
}

// ---------------------------------------------------------------------------
// zero_kernel: zero the scatter accumulator
// ---------------------------------------------------------------------------
__global__ __launch_bounds__(256) void zero_kernel() {
    int i = blockIdx.x * 256 + threadIdx.x;
    if (i < N_NODES * 16)
        reinterpret_cast<float4*>(g_msum)[i] = make_float4(0.f, 0.f, 0.f, 0.f);
}

// ---------------------------------------------------------------------------
// pq_kernel: [Ph|Qh] = feat @ [W1a|W1b], HMMA fp16, A direct from global.
// smem (words): sW [128][36]=4608 | sb1 64
// ---------------------------------------------------------------------------
#define PQ_SMEM_WORDS (4608 + 64)
#define PQ_SMEM_BYTES (PQ_SMEM_WORDS * 4)    // 18,688

__global__ __launch_bounds__(256) void pq_kernel(
    const float* __restrict__ feat,
    const float* __restrict__ W1, const float* __restrict__ b1)
{
    extern __shared__ uint32_t ps[];
    uint32_t* sW  = ps;
    float*    sb1 = reinterpret_cast<float*>(ps + 4608);
    const int tid = threadIdx.x;
    const int w   = tid >> 5;
    const int l   = tid & 31;
    const int g   = l >> 2;
    const int l4  = l & 3;

    const float4* W1v = reinterpret_cast<const float4*>(W1);
    for (int i = tid; i < 1024; i += 256) {
        const int k = i >> 4, n0 = (i & 15) * 4;
        wstore4(sW, n0, k, W1v[i]);
        wstore4(sW + 64 * 36, n0, k, W1v[1024 + i]);
    }
    if (tid < 64) sb1[tid] = b1[tid];
    __syncthreads();

    for (int grp = blockIdx.x * 8 + w; grp < NGRP; grp += gridDim.x * 8) {
        const int n0 = grp * 16;
        const float* rg  = feat + (size_t)(n0 + g) * 64;
        const float* rg8 = feat + (size_t)(n0 + g + 8) * 64;

        uint32_t Aw[16];
        #pragma unroll
        for (int kk = 0; kk < 4; kk++) {
            const int c = kk * 16 + 2 * l4;
            float2 v0 = *reinterpret_cast<const float2*>(rg + c);
            float2 v1 = *reinterpret_cast<const float2*>(rg8 + c);
            float2 v2 = *reinterpret_cast<const float2*>(rg + c + 8);
            float2 v3 = *reinterpret_cast<const float2*>(rg8 + c + 8);
            Aw[kk * 4 + 0] = h2pack(v0.x, v0.y);
            Aw[kk * 4 + 1] = h2pack(v1.x, v1.y);
            Aw[kk * 4 + 2] = h2pack(v2.x, v2.y);
            Aw[kk * 4 + 3] = h2pack(v3.x, v3.y);
        }

        #pragma unroll
        for (int pass = 0; pass < 2; pass++) {
            float acc[8][4];
            #pragma unroll
            for (int ct = 0; ct < 8; ct++)
                acc[ct][0] = acc[ct][1] = acc[ct][2] = acc[ct][3] = 0.f;

            #pragma unroll
            for (int kk = 0; kk < 4; kk++) {
                const int ko = kk * 8 + 2 * l4;
                #pragma unroll
                for (int ct = 0; ct < 8; ct++) {
                    uint2 bv = *reinterpret_cast<const uint2*>(
                        sW + ((pass * 8 + ct) * 8 + g) * 36 + ko);
                    mma16h(acc[ct], Aw[kk*4+0], Aw[kk*4+1],
                           Aw[kk*4+2], Aw[kk*4+3], bv.x, bv.y);
                }
            }

            uint32_t* dstbuf = pass ? g_Qh : g_Ph;
            #pragma unroll
            for (int ct = 0; ct < 8; ct++) {
                const int n = ct * 8 + 2 * l4;
                const float bb0 = pass ? 0.f : sb1[n];
                const float bb1 = pass ? 0.f : sb1[n + 1];
                const int j = ct * 4 + l4;
                dstbuf[(size_t)(n0 + g) * 32 + j] =
                    h2pack(acc[ct][0] + bb0, acc[ct][1] + bb1);
                dstbuf[(size_t)(n0 + g + 8) * 32 + j] =
                    h2pack(acc[ct][2] + bb0, acc[ct][3] + bb1);
            }
        }
    }
}

// ---------------------------------------------------------------------------
// Edge kernel: warp-autonomous 16-edge chunks, SOFTWARE-PIPELINED:
//   - next-chunk src/dst LDGs issued at iteration top
//   - 32 gather LDGs issued as one burst (MLP 32)
//   - next-chunk x loads issued after gathers (s/d landed by then)
//   - double-buffered warp-private A -> no trailing syncwarp
// smem words: W2f 2304 | A[8][2][576]=9216 | wl 64 | b2 64 | we 64 | be 8
// ---------------------------------------------------------------------------
#define O_W2F  0
#define O_A    2304
#define O_WL   (2304 + 9216)
#define O_B2   (O_WL + 64)
#define O_WE   (O_B2 + 64)
#define O_BE   (O_WE + 64)
#define EDGE_SMEM_WORDS (O_BE + 8)   // 11,720 words = 46,880 B static

__global__ __launch_bounds__(256, 3) void edge_kernel(
    const int* __restrict__ src, const int* __restrict__ dst,
    const float* __restrict__ x,
    const float* __restrict__ W1, const float* __restrict__ W2,
    const float* __restrict__ b2, const float* __restrict__ we,
    const float* __restrict__ be)
{
    __shared__ uint32_t sm[EDGE_SMEM_WORDS];
    float* smf = reinterpret_cast<float*>(sm);
    const int tid  = threadIdx.x;
    const int wid  = tid >> 5;
    const int lane = tid & 31;

    const float4* W2v = reinterpret_cast<const float4*>(W2);
    for (int i = tid; i < 1024; i += 256) {
        const int k = i >> 4, n0 = (i & 15) * 4;
        wstore4(sm + O_W2F, n0, k, W2v[i]);
    }
    if (tid < 64) {
        smf[O_WL + tid] = W1[128 * 64 + tid];
        smf[O_B2 + tid] = b2[tid];
        smf[O_WE + tid] = we[tid];
    }
    if (tid == 0) smf[O_BE] = be[0];
    __syncthreads();

    const int g  = lane >> 2;
    const int l4 = lane & 3;
    const bool even = !(l4 & 1);
    const int kposl = kpos(lane);
    const float wlx = smf[O_WL + 2 * lane];
    const float wly = smf[O_WL + 2 * lane + 1];
    const float be0 = smf[O_BE];
    const uint32_t* W2u = sm + O_W2F;
    uint32_t* Abase = sm + O_A + wid * 1152;

    const int stride = gridDim.x * 8;
    int c = blockIdx.x * 8 + wid;

    // ---- prologue: current-chunk meta ----
    int sC = 0, dC = 0;
    float sqC = 0.f;
    if (c < N_CHUNK && lane < 16) {
        sC = src[c * 16 + lane];
        dC = dst[c * 16 + lane];
        float ax = x[3 * sC], ay = x[3 * sC + 1], az = x[3 * sC + 2];
        float bx = x[3 * dC], by = x[3 * dC + 1], bz = x[3 * dC + 2];
        float dx = ax - bx, dy = ay - by, dz = az - bz;
        sqC = dx * dx + dy * dy + dz * dz;
    }

    int buf = 0;
    for (; c < N_CHUNK; c += stride) {
        const int cn = c + stride;

        // ---- stage 1: issue next-chunk src/dst loads (latency hidden below)
        int sN = 0, dN = 0;
        if (cn < N_CHUNK && lane < 16) {
            sN = src[cn * 16 + lane];
            dN = dst[cn * 16 + lane];
        }

        // ---- stage 2: full-width gather burst for current chunk (MLP 32)
        uint32_t pv[16], qv[16];
        #pragma unroll
        for (int j = 0; j < 16; j++) {
            const int s = __shfl_sync(0xffffffffu, sC, j);
            const int d = __shfl_sync(0xffffffffu, dC, j);
            pv[j] = g_Ph[(size_t)s * 32 + lane];
            qv[j] = g_Qh[(size_t)d * 32 + lane];
        }

        // ---- stage 3: next-chunk x loads (sN/dN have landed by now)
        float sqN = 0.f;
        if (cn < N_CHUNK && lane < 16) {
            float ax = x[3 * sN], ay = x[3 * sN + 1], az = x[3 * sN + 2];
            float bx = x[3 * dN], by = x[3 * dN + 1], bz = x[3 * dN + 2];
            float dx = ax - bx, dy = ay - by, dz = az - bz;
            sqN = dx * dx + dy * dy + dz * dz;
        }

        // ---- stage 4: h1 = relu(P+Q+sq*wl) -> A[buf]
        uint32_t* Aw = Abase + buf * 576;
        #pragma unroll
        for (int j = 0; j < 16; j++) {
            const float sq = __shfl_sync(0xffffffffu, sqC, j);
            float2 p2 = h2unpack(pv[j]);
            float2 q2 = h2unpack(qv[j]);
            float h0 = fmaxf(p2.x + q2.x + sq * wlx, 0.f);
            float h1 = fmaxf(p2.y + q2.y + sq * wly, 0.f);
            Aw[j * 36 + kposl] = h2pack(h0, h1);
        }
        __syncwarp();

        // ---- stage 5: layer 2 (32 HMMA on own 16 edges)
        float acc[8][4];
        #pragma unroll
        for (int ct = 0; ct < 8; ct++)
            acc[ct][0] = acc[ct][1] = acc[ct][2] = acc[ct][3] = 0.f;

        #pragma unroll
        for (int kk = 0; kk < 4; kk++) {
            const int ko = kk * 8 + 2 * l4;
            uint2 alo = *reinterpret_cast<const uint2*>(Aw + g * 36 + ko);
            uint2 ahi = *reinterpret_cast<const uint2*>(Aw + (g + 8) * 36 + ko);
            #pragma unroll
            for (int ct = 0; ct < 8; ct++) {
                uint2 bv = *reinterpret_cast<const uint2*>(
                    W2u + (ct * 8 + g) * 36 + ko);
                mma16h(acc[ct], alo.x, ahi.x, alo.y, ahi.y, bv.x, bv.y);
            }
        }

        // ---- stage 6: epilogue m = relu(d2+b2), gate
        float pg = 0.f, pg8 = 0.f;
        #pragma unroll
        for (int ct = 0; ct < 8; ct++) {
            const int c0 = ct * 8 + 2 * l4;
            const float bb0 = smf[O_B2 + c0], bb1 = smf[O_B2 + c0 + 1];
            const float w0 = smf[O_WE + c0],  w1 = smf[O_WE + c0 + 1];
            acc[ct][0] = fmaxf(acc[ct][0] + bb0, 0.f);
            acc[ct][1] = fmaxf(acc[ct][1] + bb1, 0.f);
            acc[ct][2] = fmaxf(acc[ct][2] + bb0, 0.f);
            acc[ct][3] = fmaxf(acc[ct][3] + bb1, 0.f);
            pg  = fmaf(acc[ct][0], w0, fmaf(acc[ct][1], w1, pg));
            pg8 = fmaf(acc[ct][2], w0, fmaf(acc[ct][3], w1, pg8));
        }
        pg  += __shfl_xor_sync(0xffffffffu, pg, 1);
        pg  += __shfl_xor_sync(0xffffffffu, pg, 2);
        pg8 += __shfl_xor_sync(0xffffffffu, pg8, 1);
        pg8 += __shfl_xor_sync(0xffffffffu, pg8, 2);
        const float G  = 1.f / (1.f + __expf(-(pg + be0)));
        const float G8 = 1.f / (1.f + __expf(-(pg8 + be0)));

        // ---- stage 7: scatter (dst via shfl, ct-pairs -> full-width red4)
        const int dg  = __shfl_sync(0xffffffffu, dC, g);
        const int dg8 = __shfl_sync(0xffffffffu, dC, g + 8);
        float* bp  = g_msum + (size_t)dg * 64;
        float* bp8 = g_msum + (size_t)dg8 * 64;
        #pragma unroll
        for (int a = 0; a < 4; a++) {
            const int ct0 = 2 * a, ct1 = 2 * a + 1;
            float s00 = acc[ct0][0] * G,  s01 = acc[ct0][1] * G;
            float s02 = acc[ct0][2] * G8, s03 = acc[ct0][3] * G8;
            float s10 = acc[ct1][0] * G,  s11 = acc[ct1][1] * G;
            float s12 = acc[ct1][2] * G8, s13 = acc[ct1][3] * G8;
            float x0 = __shfl_xor_sync(0xffffffffu, s00, 1);
            float x1 = __shfl_xor_sync(0xffffffffu, s01, 1);
            float x2 = __shfl_xor_sync(0xffffffffu, s02, 1);
            float x3 = __shfl_xor_sync(0xffffffffu, s03, 1);
            float y0 = __shfl_xor_sync(0xffffffffu, s10, 1);
            float y1 = __shfl_xor_sync(0xffffffffu, s11, 1);
            float y2 = __shfl_xor_sync(0xffffffffu, s12, 1);
            float y3 = __shfl_xor_sync(0xffffffffu, s13, 1);
            const int chb = (even ? ct0 : ct1) * 8 + 2 * (l4 & ~1);
            float a0 = even ? s00 : y0,  a1 = even ? s01 : y1;
            float a2 = even ? x0  : s10, a3 = even ? x1  : s11;
            float b0 = even ? s02 : y2,  b1 = even ? s03 : y3;
            float b2 = even ? x2  : s12, b3 = even ? x3  : s13;
            red4(bp + chb,  a0, a1, a2, a3);
            red4(bp8 + chb, b0, b1, b2, b3);
        }

        // ---- rotate pipeline state (double-buffered A: no syncwarp needed)
        sC = sN; dC = dN; sqC = sqN;
        buf ^= 1;
    }
}

// ---------------------------------------------------------------------------
// node_kernel: HMMA fp16; layer-1 A direct from global; H staged per-warp.
// smem words: sU1h 2304 | sU2h 2304 | c1 64 | c2 64 | per-warp H 576 x 8
// ---------------------------------------------------------------------------
#define NODE_SMEM_WORDS (2304 + 2304 + 64 + 64 + 8 * 576)
#define NODE_SMEM_BYTES (NODE_SMEM_WORDS * 4)   // 37,376

__global__ __launch_bounds__(256, 4) void node_kernel(
    const float* __restrict__ feat,
    const float* __restrict__ U1, const float* __restrict__ c1,
    const float* __restrict__ U2, const float* __restrict__ c2,
    float* __restrict__ out)
{
    extern __shared__ uint32_t ns[];
    uint32_t* sU1h = ns;
    uint32_t* sU2h = ns + 2304;
    float*    sc1  = reinterpret_cast<float*>(ns + 4608);
    float*    sc2  = reinterpret_cast<float*>(ns + 4672);
    const int tid = threadIdx.x;
    const int w   = tid >> 5;
    const int l   = tid & 31;
    const int g   = l >> 2;
    const int l4  = l & 3;
    uint32_t* pH = ns + 4736 + w * 576;

    const float4* U1v = reinterpret_cast<const float4*>(U1);
    const float4* U2v = reinterpret_cast<const float4*>(U2);
    for (int i = tid; i < 1024; i += 256) {
        const int k = i >> 4, n0 = (i & 15) * 4;
        wstore4(sU1h, n0, k, U1v[i]);
        wstore4(sU2h, n0, k, U2v[i]);
    }
    if (tid < 64) { sc1[tid] = c1[tid]; sc2[tid] = c2[tid]; }
    __syncthreads();

    for (int grp = blockIdx.x * 8 + w; grp < NGRP; grp += gridDim.x * 8) {
        const int n0 = grp * 16;
        const float* fg  = feat + (size_t)(n0 + g) * 64;
        const float* fg8 = feat + (size_t)(n0 + g + 8) * 64;
        const float* mg  = g_msum + (size_t)(n0 + g) * 64;
        const float* mg8 = g_msum + (size_t)(n0 + g + 8) * 64;

        uint32_t Aw[16];
        #pragma unroll
        for (int kk = 0; kk < 4; kk++) {
            const int c = kk * 16 + 2 * l4;
            float2 f0 = *reinterpret_cast<const float2*>(fg + c);
            float2 m0 = *reinterpret_cast<const float2*>(mg + c);
            float2 f1 = *reinterpret_cast<const float2*>(fg8 + c);
            float2 m1 = *reinterpret_cast<const float2*>(mg8 + c);
            float2 f2 = *reinterpret_cast<const float2*>(fg + c + 8);
            float2 m2 = *reinterpret_cast<const float2*>(mg + c + 8);
            float2 f3 = *reinterpret_cast<const float2*>(fg8 + c + 8);
            float2 m3 = *reinterpret_cast<const float2*>(mg8 + c + 8);
            Aw[kk * 4 + 0] = h2pack(f0.x + m0.x, f0.y + m0.y);
            Aw[kk * 4 + 1] = h2pack(f1.x + m1.x, f1.y + m1.y);
            Aw[kk * 4 + 2] = h2pack(f2.x + m2.x, f2.y + m2.y);
            Aw[kk * 4 + 3] = h2pack(f3.x + m3.x, f3.y + m3.y);
        }

        float acc[8][4];
        #pragma unroll
        for (int ct = 0; ct < 8; ct++)
            acc[ct][0] = acc[ct][1] = acc[ct][2] = acc[ct][3] = 0.f;
        #pragma unroll
        for (int kk = 0; kk < 4; kk++) {
            #pragma unroll
            for (int ct = 0; ct < 8; ct++) {
                uint2 bv = *reinterpret_cast<const uint2*>(
                    sU1h + (ct * 8 + g) * 36 + kk * 8 + 2 * l4);
                mma16h(acc[ct], Aw[kk*4+0], Aw[kk*4+1],
                       Aw[kk*4+2], Aw[kk*4+3], bv.x, bv.y);
            }
        }
        // epilogue 1: relu -> H staged in smem
        #pragma unroll
        for (int ct = 0; ct < 8; ct++) {
            const int c0 = ct * 8 + 2 * l4;
            const int j  = ct * 4 + l4;
            const float bb0 = sc1[c0], bb1 = sc1[c0 + 1];
            pH[g * 36 + kpos(j)] =
                h2pack(fmaxf(acc[ct][0] + bb0, 0.f), fmaxf(acc[ct][1] + bb1, 0.f));
            pH[(g + 8) * 36 + kpos(j)] =
                h2pack(fmaxf(acc[ct][2] + bb0, 0.f), fmaxf(acc[ct][3] + bb1, 0.f));
        }
        __syncwarp();

        // layer 2
        #pragma unroll
        for (int ct = 0; ct < 8; ct++)
            acc[ct][0] = acc[ct][1] = acc[ct][2] = acc[ct][3] = 0.f;
        #pragma unroll
        for (int kk = 0; kk < 4; kk++) {
            const int ko = kk * 8 + 2 * l4;
            uint2 alo = *reinterpret_cast<const uint2*>(pH + g * 36 + ko);
            uint2 ahi = *reinterpret_cast<const uint2*>(pH + (g + 8) * 36 + ko);
            #pragma unroll
            for (int ct = 0; ct < 8; ct++) {
                uint2 bv = *reinterpret_cast<const uint2*>(
                    sU2h + (ct * 8 + g) * 36 + ko);
                mma16h(acc[ct], alo.x, ahi.x, alo.y, ahi.y, bv.x, bv.y);
            }
        }
        // epilogue 2: + c2 + feat residual (fp32 out)
        #pragma unroll
        for (int ct = 0; ct < 8; ct++) {
            const int c0 = ct * 8 + 2 * l4;
            const float bb0 = sc2[c0], bb1 = sc2[c0 + 1];
            float2 f0 = *reinterpret_cast<const float2*>(fg + c0);
            float2 f1 = *reinterpret_cast<const float2*>(fg8 + c0);
            *reinterpret_cast<float2*>(out + (size_t)(n0 + g) * 64 + c0) =
                make_float2(acc[ct][0] + bb0 + f0.x, acc[ct][1] + bb1 + f0.y);
            *reinterpret_cast<float2*>(out + (size_t)(n0 + g + 8) * 64 + c0) =
                make_float2(acc[ct][2] + bb0 + f1.x, acc[ct][3] + bb1 + f1.y);
        }
        __syncwarp();
    }
}

// ---------------------------------------------------------------------------
extern "C" void kernel_launch(void* const* d_in, const int* in_sizes, int n_in,
                              void* d_out, int out_size)
{
    const float* feat = (const float*)d_in[0];
    const float* x    = (const float*)d_in[1];
    const int*   src  = (const int*)  d_in[2];
    const int*   dst  = (const int*)  d_in[3];
    const float* W1   = (const float*)d_in[4];
    const float* b1   = (const float*)d_in[5];
    const float* W2   = (const float*)d_in[6];
    const float* b2   = (const float*)d_in[7];
    const float* we   = (const float*)d_in[8];
    const float* be   = (const float*)d_in[9];
    const float* U1   = (const float*)d_in[10];
    const float* c1   = (const float*)d_in[11];
    const float* U2   = (const float*)d_in[12];
    const float* c2   = (const float*)d_in[13];
    float* out = (float*)d_out;

    cudaFuncSetAttribute(pq_kernel,
                         cudaFuncAttributeMaxDynamicSharedMemorySize,
                         PQ_SMEM_BYTES);
    cudaFuncSetAttribute(node_kernel,
                         cudaFuncAttributeMaxDynamicSharedMemorySize,
                         NODE_SMEM_BYTES);

    zero_kernel<<<(N_NODES * 16 + 255) / 256, 256>>>();
    pq_kernel<<<391, 256, PQ_SMEM_BYTES>>>(feat, W1, b1);
    edge_kernel<<<EDGE_CTAS, 256>>>(src, dst, x, W1, W2, b2, we, be);
    node_kernel<<<592, 256, NODE_SMEM_BYTES>>>(feat, U1, c1, U2, c2, out);
}